// round 7
// baseline (speedup 1.0000x reference)
#include <cuda_runtime.h>
#include <cstdint>

// Problem shapes (fixed by the dataset)
constexpr int Bdim = 8;
constexpr int T    = 512;
constexpr int D    = 1024;
constexpr int E    = 64;

// Tiling
constexpr int BM = 128;
constexpr int BN = 128;
constexpr int BK = 32;
constexpr int THREADS = 256;         // 8 warps: 4 in M x 2 in N, warp tile 32x64
constexpr int AS_STRIDE = BK + 4;    // 36 floats
constexpr int BS_STRIDE = BN + 8;    // 136 floats
constexpr int SMEM_FLOATS = 2 * BM * AS_STRIDE + 2 * BK * BS_STRIDE; // 17920
constexpr int SMEM_BYTES  = SMEM_FLOATS * 4;                          // 71680

// RNA-rounded copy of x (tf32-exact, so raw LDS feed == RNA rounding)
__device__ float g_x_round[(size_t)Bdim * T * D];

__device__ __forceinline__ void cp16(float* smem_ptr, const float* gmem_ptr) {
    uint32_t s = (uint32_t)__cvta_generic_to_shared(smem_ptr);
    asm volatile("cp.async.cg.shared.global [%0], [%1], 16;" :: "r"(s), "l"(gmem_ptr));
}

__device__ __forceinline__ uint32_t f2tf32(float f) {
    uint32_t r;
    asm("cvt.rna.tf32.f32 %0, %1;" : "=r"(r) : "f"(f));
    return r;
}

__device__ __forceinline__ void mma_tf32(float* c, const uint32_t* a, const uint32_t* b) {
    asm volatile(
        "mma.sync.aligned.m16n8k8.row.col.f32.tf32.tf32.f32 "
        "{%0,%1,%2,%3}, {%4,%5,%6,%7}, {%8,%9}, {%0,%1,%2,%3};\n"
        : "+f"(c[0]), "+f"(c[1]), "+f"(c[2]), "+f"(c[3])
        : "r"(a[0]), "r"(a[1]), "r"(a[2]), "r"(a[3]), "r"(b[0]), "r"(b[1]));
}

// idx dtype auto-detect (proven in R3): int32 unless all high words zero.
__device__ __forceinline__ int load_expert_idx(const void* idx_raw, int pos) {
    const int* p32 = (const int*)idx_raw;
    bool is64 = true;
    #pragma unroll
    for (int j = 1; j < 16; j += 2) is64 &= (p32[j] == 0);
    int e = is64 ? p32[2 * pos] : p32[pos];
    return min(max(e, 0), E - 1);
}

// Pre-kernel: RNA-round x into scratch once (removes all cvt from mainloop A path)
__global__ void round_x_kernel(const float* __restrict__ x) {
    const int n4 = (Bdim * T * D) / 4;
    const float4* src = (const float4*)x;
    float4* dst = (float4*)g_x_round;
    for (int i = blockIdx.x * blockDim.x + threadIdx.x; i < n4; i += gridDim.x * blockDim.x) {
        float4 v = src[i];
        v.x = __uint_as_float(f2tf32(v.x));
        v.y = __uint_as_float(f2tf32(v.y));
        v.z = __uint_as_float(f2tf32(v.z));
        v.w = __uint_as_float(f2tf32(v.w));
        dst[i] = v;
    }
}

extern __shared__ float smem[];

__global__ void __launch_bounds__(THREADS, 2)
expertbank_kernel(const float* __restrict__ w,
                  const float* __restrict__ Wb,
                  const float* __restrict__ bb,
                  const void*  __restrict__ idx,
                  float* __restrict__ out)
{
    const int tn = blockIdx.x;   // N tile (0..7)
    const int tm = blockIdx.y;   // M tile (0..3)
    const int b  = blockIdx.z;   // batch

    const int tid  = threadIdx.x;
    const int lane = tid & 31;
    const int warp = tid >> 5;
    const int wm = warp & 3;     // warp row (M)
    const int wn = warp >> 2;    // warp col (N)

    const float* xblk = g_x_round + ((size_t)b * T + (size_t)tm * BM) * D;

    float* As0 = smem;                         // 2 x [BM][AS_STRIDE]
    float* Bs0 = smem + 2 * BM * AS_STRIDE;    // 2 x [BK][BS_STRIDE]

    const int KT = D / BK;  // 32

    for (int ke = 0; ke < 2; ++ke) {
        const int   e   = load_expert_idx(idx, b * 2 + ke);
        const float wgt = w[b * 2 + ke];
        const float* Wp = Wb + (size_t)e * D * D + (size_t)tn * BN;
        const float* bp = bb + (size_t)e * D + (size_t)tn * BN;

        float acc[2][8][4];
        #pragma unroll
        for (int mi = 0; mi < 2; ++mi)
            #pragma unroll
            for (int ni = 0; ni < 8; ++ni)
                #pragma unroll
                for (int j = 0; j < 4; ++j)
                    acc[mi][ni][j] = 0.f;

        auto load_ab = [&](int kt, int buf) {
            float* Ad = As0 + buf * (BM * AS_STRIDE);
            const float* Ag = xblk + kt * BK;
            #pragma unroll
            for (int i = 0; i < 4; ++i) {
                int lin = tid + i * THREADS;          // 0..1023
                int m  = lin >> 3;
                int kv = (lin & 7) << 2;
                cp16(Ad + m * AS_STRIDE + kv, Ag + (size_t)m * D + kv);
            }
            float* Bd = Bs0 + buf * (BK * BS_STRIDE);
            const float* Bg = Wp + (size_t)kt * BK * D;
            #pragma unroll
            for (int i = 0; i < 4; ++i) {
                int lin = tid + i * THREADS;
                int k  = lin >> 5;
                int nv = (lin & 31) << 2;
                cp16(Bd + k * BS_STRIDE + nv, Bg + (size_t)k * D + nv);
            }
        };

        // prologue
        load_ab(0, 0);
        asm volatile("cp.async.commit_group;" ::: "memory");

        for (int kt = 0; kt < KT; ++kt) {
            asm volatile("cp.async.wait_group 0;" ::: "memory");
            __syncthreads();
            if (kt + 1 < KT) {
                load_ab(kt + 1, (kt + 1) & 1);
                asm volatile("cp.async.commit_group;" ::: "memory");
            }
            const float* Ab = As0 + (kt & 1) * (BM * AS_STRIDE);
            const float* Bb = Bs0 + (kt & 1) * (BK * BS_STRIDE);

            #pragma unroll
            for (int kk = 0; kk < BK / 8; ++kk) {
                // A is pre-rounded (RNA); B fed raw -> hw tf32 truncation.
                uint32_t af[2][4];
                #pragma unroll
                for (int mi = 0; mi < 2; ++mi) {
                    int r = wm * 32 + mi * 16 + (lane >> 2);
                    int c = kk * 8 + (lane & 3);
                    const float* A0 = Ab + r * AS_STRIDE + c;
                    af[mi][0] = __float_as_uint(A0[0]);
                    af[mi][1] = __float_as_uint(A0[8 * AS_STRIDE]);
                    af[mi][2] = __float_as_uint(A0[4]);
                    af[mi][3] = __float_as_uint(A0[8 * AS_STRIDE + 4]);
                }
                uint32_t bf[8][2];
                #pragma unroll
                for (int ni = 0; ni < 8; ++ni) {
                    int c  = wn * 64 + ni * 8 + (lane >> 2);
                    int k0 = kk * 8 + (lane & 3);
                    const float* B0 = Bb + k0 * BS_STRIDE + c;
                    bf[ni][0] = __float_as_uint(B0[0]);
                    bf[ni][1] = __float_as_uint(B0[4 * BS_STRIDE]);
                }
                #pragma unroll
                for (int mi = 0; mi < 2; ++mi)
                    #pragma unroll
                    for (int ni = 0; ni < 8; ++ni)
                        mma_tf32(acc[mi][ni], af[mi], bf[ni]);
            }
        }
        __syncthreads();

        // epilogue (two-pass combine, no out_acc registers):
        //   ke==0: out  = w0 * relu(y0 + b0)
        //   ke==1: out += w1 * relu(y1 + b1)
        float* ob = out + ((size_t)b * T + (size_t)tm * BM) * D + (size_t)tn * BN;
        #pragma unroll
        for (int mi = 0; mi < 2; ++mi) {
            #pragma unroll
            for (int ni = 0; ni < 8; ++ni) {
                int r0 = wm * 32 + mi * 16 + (lane >> 2);
                int c  = wn * 64 + ni * 8 + (lane & 3) * 2;
                float bias0 = bp[c];
                float bias1 = bp[c + 1];
                float v00 = wgt * fmaxf(acc[mi][ni][0] + bias0, 0.f);
                float v01 = wgt * fmaxf(acc[mi][ni][1] + bias1, 0.f);
                float v10 = wgt * fmaxf(acc[mi][ni][2] + bias0, 0.f);
                float v11 = wgt * fmaxf(acc[mi][ni][3] + bias1, 0.f);
                float2* p0 = reinterpret_cast<float2*>(&ob[(size_t)r0 * D + c]);
                float2* p1 = reinterpret_cast<float2*>(&ob[(size_t)(r0 + 8) * D + c]);
                if (ke == 0) {
                    *p0 = make_float2(v00, v01);
                    *p1 = make_float2(v10, v11);
                } else {
                    float2 o0 = *p0, o1 = *p1;
                    *p0 = make_float2(o0.x + v00, o0.y + v01);
                    *p1 = make_float2(o1.x + v10, o1.y + v11);
                }
            }
        }
        __syncthreads();
    }
}

extern "C" void kernel_launch(void* const* d_in, const int* in_sizes, int n_in,
                              void* d_out, int out_size) {
    const float* x   = (const float*)d_in[0];
    const float* w   = (const float*)d_in[1];
    const float* Wb  = (const float*)d_in[2];
    const float* bb  = (const float*)d_in[3];
    const void*  idx = (const void*)d_in[4];
    float* out = (float*)d_out;

    round_x_kernel<<<2048, 256>>>(x);

    cudaFuncSetAttribute(expertbank_kernel,
                         cudaFuncAttributeMaxDynamicSharedMemorySize, SMEM_BYTES);
    dim3 grid(D / BN, T / BM, Bdim);  // (8, 4, 8) = 256 blocks
    expertbank_kernel<<<grid, THREADS, SMEM_BYTES>>>(w, Wb, bb, idx, out);
}

// round 8
// speedup vs baseline: 1.4672x; 1.4672x over previous
#include <cuda_runtime.h>
#include <cstdint>

// Problem shapes (fixed by the dataset)
constexpr int Bdim = 8;
constexpr int T    = 512;
constexpr int D    = 1024;
constexpr int E    = 64;

// Tiling
constexpr int BM = 128;
constexpr int BN = 128;
constexpr int BK = 64;               // bigger K-slab: fewer syncs/waits
constexpr int THREADS = 256;         // 8 warps: 4 in M x 2 in N, warp tile 32x64
constexpr int AS_STRIDE = BK + 4;    // 68  (68 mod 32 = 4 -> conflict-free A frags)
constexpr int BS_STRIDE = BN + 8;    // 136 (136 mod 32 = 8 -> conflict-free B frags)
constexpr int SMEM_FLOATS = 2 * BM * AS_STRIDE + 2 * BK * BS_STRIDE; // 34816
constexpr int SMEM_BYTES  = SMEM_FLOATS * 4;                          // 139264

// RNA-rounded copy of x (tf32-exact, so raw LDS feed == RNA rounding)
__device__ float g_x_round[(size_t)Bdim * T * D];

__device__ __forceinline__ void cp16(float* smem_ptr, const float* gmem_ptr) {
    uint32_t s = (uint32_t)__cvta_generic_to_shared(smem_ptr);
    asm volatile("cp.async.cg.shared.global [%0], [%1], 16;" :: "r"(s), "l"(gmem_ptr));
}

__device__ __forceinline__ uint32_t f2tf32(float f) {
    uint32_t r;
    asm("cvt.rna.tf32.f32 %0, %1;" : "=r"(r) : "f"(f));
    return r;
}

__device__ __forceinline__ void mma_tf32(float* c, const uint32_t* a, const uint32_t* b) {
    asm volatile(
        "mma.sync.aligned.m16n8k8.row.col.f32.tf32.tf32.f32 "
        "{%0,%1,%2,%3}, {%4,%5,%6,%7}, {%8,%9}, {%0,%1,%2,%3};\n"
        : "+f"(c[0]), "+f"(c[1]), "+f"(c[2]), "+f"(c[3])
        : "r"(a[0]), "r"(a[1]), "r"(a[2]), "r"(a[3]), "r"(b[0]), "r"(b[1]));
}

// idx dtype auto-detect (proven in R3): int32 unless all high words zero.
__device__ __forceinline__ int load_expert_idx(const void* idx_raw, int pos) {
    const int* p32 = (const int*)idx_raw;
    bool is64 = true;
    #pragma unroll
    for (int j = 1; j < 16; j += 2) is64 &= (p32[j] == 0);
    int e = is64 ? p32[2 * pos] : p32[pos];
    return min(max(e, 0), E - 1);
}

// Pre-kernel: RNA-round x once (A path then needs no cvt in the mainloop)
__global__ void round_x_kernel(const float* __restrict__ x) {
    const int n4 = (Bdim * T * D) / 4;
    const float4* src = (const float4*)x;
    float4* dst = (float4*)g_x_round;
    for (int i = blockIdx.x * blockDim.x + threadIdx.x; i < n4; i += gridDim.x * blockDim.x) {
        float4 v = src[i];
        v.x = __uint_as_float(f2tf32(v.x));
        v.y = __uint_as_float(f2tf32(v.y));
        v.z = __uint_as_float(f2tf32(v.z));
        v.w = __uint_as_float(f2tf32(v.w));
        dst[i] = v;
    }
}

extern __shared__ float smem[];

__global__ void __launch_bounds__(THREADS, 1)
expertbank_kernel(const float* __restrict__ w,
                  const float* __restrict__ Wb,
                  const float* __restrict__ bb,
                  const void*  __restrict__ idx,
                  float* __restrict__ out)
{
    const int tn = blockIdx.x;   // N tile (0..7)
    const int tm = blockIdx.y;   // M tile (0..3)
    const int b  = blockIdx.z;   // batch

    const int tid  = threadIdx.x;
    const int lane = tid & 31;
    const int warp = tid >> 5;
    const int wm = warp & 3;     // warp row (M)
    const int wn = warp >> 2;    // warp col (N)

    const float* xblk = g_x_round + ((size_t)b * T + (size_t)tm * BM) * D;

    float* As0 = smem;                         // 2 x [BM][AS_STRIDE]
    float* Bs0 = smem + 2 * BM * AS_STRIDE;    // 2 x [BK][BS_STRIDE]

    float out_acc[2][8][4];
    #pragma unroll
    for (int mi = 0; mi < 2; ++mi)
        #pragma unroll
        for (int ni = 0; ni < 8; ++ni)
            #pragma unroll
            for (int j = 0; j < 4; ++j)
                out_acc[mi][ni][j] = 0.f;

    const int KT = D / BK;  // 16

    // per-warp fragment base rows/cols
    const int ar = wm * 32 + (lane >> 2);
    const int bc = wn * 64 + (lane >> 2);

    for (int ke = 0; ke < 2; ++ke) {
        const int   e   = load_expert_idx(idx, b * 2 + ke);
        const float wgt = w[b * 2 + ke];
        const float* Wp = Wb + (size_t)e * D * D + (size_t)tn * BN;
        const float* bp = bb + (size_t)e * D + (size_t)tn * BN;

        float acc[2][8][4];
        #pragma unroll
        for (int mi = 0; mi < 2; ++mi)
            #pragma unroll
            for (int ni = 0; ni < 8; ++ni)
                #pragma unroll
                for (int j = 0; j < 4; ++j)
                    acc[mi][ni][j] = 0.f;

        auto load_ab = [&](int kt, int buf) {
            float* Ad = As0 + buf * (BM * AS_STRIDE);
            const float* Ag = xblk + kt * BK;
            #pragma unroll
            for (int i = 0; i < 8; ++i) {
                int lin = tid + i * THREADS;          // 0..2047
                int m  = lin >> 4;                    // 128 rows, 16 float4/row
                int kv = (lin & 15) << 2;
                cp16(Ad + m * AS_STRIDE + kv, Ag + (size_t)m * D + kv);
            }
            float* Bd = Bs0 + buf * (BK * BS_STRIDE);
            const float* Bg = Wp + (size_t)kt * BK * D;
            #pragma unroll
            for (int i = 0; i < 8; ++i) {
                int lin = tid + i * THREADS;          // 0..2047
                int k  = lin >> 5;                    // 64 rows, 32 float4/row
                int nv = (lin & 31) << 2;
                cp16(Bd + k * BS_STRIDE + nv, Bg + (size_t)k * D + nv);
            }
        };

        // prologue
        load_ab(0, 0);
        asm volatile("cp.async.commit_group;" ::: "memory");

        for (int kt = 0; kt < KT; ++kt) {
            asm volatile("cp.async.wait_group 0;" ::: "memory");
            __syncthreads();
            if (kt + 1 < KT) {
                load_ab(kt + 1, (kt + 1) & 1);
                asm volatile("cp.async.commit_group;" ::: "memory");
            }
            const float* Ab = As0 + (kt & 1) * (BM * AS_STRIDE);
            const float* Bb = Bs0 + (kt & 1) * (BK * BS_STRIDE);

            // fragment double-buffer across the 8 kk steps
            uint32_t af[2][2][4];   // [buf][mi][4]
            uint32_t bf[2][8][2];   // [buf][ni][2]

            auto ldfrag = [&](int kk, int fb) {
                const int c = kk * 8 + (lane & 3);
                #pragma unroll
                for (int mi = 0; mi < 2; ++mi) {
                    const float* A0 = Ab + (ar + mi * 16) * AS_STRIDE + c;
                    af[fb][mi][0] = __float_as_uint(A0[0]);
                    af[fb][mi][1] = __float_as_uint(A0[8 * AS_STRIDE]);
                    af[fb][mi][2] = __float_as_uint(A0[4]);
                    af[fb][mi][3] = __float_as_uint(A0[8 * AS_STRIDE + 4]);
                }
                const int k0 = kk * 8 + (lane & 3);
                #pragma unroll
                for (int ni = 0; ni < 8; ++ni) {
                    const float* B0 = Bb + k0 * BS_STRIDE + bc + ni * 8;
                    bf[fb][ni][0] = __float_as_uint(B0[0]);
                    bf[fb][ni][1] = __float_as_uint(B0[4 * BS_STRIDE]);
                }
            };

            ldfrag(0, 0);
            #pragma unroll
            for (int kk = 0; kk < BK / 8; ++kk) {
                const int cur = kk & 1;
                if (kk + 1 < BK / 8) ldfrag(kk + 1, cur ^ 1);
                #pragma unroll
                for (int mi = 0; mi < 2; ++mi)
                    #pragma unroll
                    for (int ni = 0; ni < 8; ++ni)
                        mma_tf32(acc[mi][ni], af[cur][mi], bf[cur][ni]);
            }
        }
        __syncthreads();

        // fold into out_acc: out_acc += w * relu(acc + bias)
        #pragma unroll
        for (int mi = 0; mi < 2; ++mi) {
            #pragma unroll
            for (int ni = 0; ni < 8; ++ni) {
                int col = wn * 64 + ni * 8 + (lane & 3) * 2;
                float bias0 = bp[col];
                float bias1 = bp[col + 1];
                out_acc[mi][ni][0] += wgt * fmaxf(acc[mi][ni][0] + bias0, 0.f);
                out_acc[mi][ni][1] += wgt * fmaxf(acc[mi][ni][1] + bias1, 0.f);
                out_acc[mi][ni][2] += wgt * fmaxf(acc[mi][ni][2] + bias0, 0.f);
                out_acc[mi][ni][3] += wgt * fmaxf(acc[mi][ni][3] + bias1, 0.f);
            }
        }
    }

    // final store
    float* ob = out + ((size_t)b * T + (size_t)tm * BM) * D + (size_t)tn * BN;
    #pragma unroll
    for (int mi = 0; mi < 2; ++mi) {
        #pragma unroll
        for (int ni = 0; ni < 8; ++ni) {
            int r0 = wm * 32 + mi * 16 + (lane >> 2);
            int c  = wn * 64 + ni * 8 + (lane & 3) * 2;
            *reinterpret_cast<float2*>(&ob[(size_t)r0 * D + c]) =
                make_float2(out_acc[mi][ni][0], out_acc[mi][ni][1]);
            *reinterpret_cast<float2*>(&ob[(size_t)(r0 + 8) * D + c]) =
                make_float2(out_acc[mi][ni][2], out_acc[mi][ni][3]);
        }
    }
}

extern "C" void kernel_launch(void* const* d_in, const int* in_sizes, int n_in,
                              void* d_out, int out_size) {
    const float* x   = (const float*)d_in[0];
    const float* w   = (const float*)d_in[1];
    const float* Wb  = (const float*)d_in[2];
    const float* bb  = (const float*)d_in[3];
    const void*  idx = (const void*)d_in[4];
    float* out = (float*)d_out;

    round_x_kernel<<<2048, 256>>>(x);

    cudaFuncSetAttribute(expertbank_kernel,
                         cudaFuncAttributeMaxDynamicSharedMemorySize, SMEM_BYTES);
    dim3 grid(D / BN, T / BM, Bdim);  // (8, 4, 8) = 256 blocks
    expertbank_kernel<<<grid, THREADS, SMEM_BYTES>>>(w, Wb, bb, idx, out);
}